// round 3
// baseline (speedup 1.0000x reference)
#include <cuda_runtime.h>

#define NBLOCKS 1184
#define NTHREADS 256

__device__ float        g_partials[NBLOCKS];
__device__ unsigned int g_counter = 0;   // self-resetting via atomicInc wrap

__device__ __forceinline__ float4 ldcs4(const float4* p) {
    return __ldcs(p);   // evict-streaming: single-use data, don't hold in L2/L1
}

__global__ __launch_bounds__(NTHREADS)
void qsum_fused_kernel(const float* __restrict__ phi,
                       const float* __restrict__ w,
                       long long n4, long long n_total,
                       float bias, float inv_N,
                       float* __restrict__ out) {
    const float4* __restrict__ p4 = reinterpret_cast<const float4*>(phi);
    const float4* __restrict__ w4 = reinterpret_cast<const float4*>(w);

    float acc0 = 0.0f, acc1 = 0.0f;
    long long tid    = (long long)blockIdx.x * NTHREADS + threadIdx.x;
    long long stride = (long long)gridDim.x * NTHREADS;

    // Main loop, 2x unrolled: 4 front-batched LDG.128 (64B in flight / thread / iter)
    long long i = tid;
    for (; i + stride < n4; i += 2 * stride) {
        float4 a0 = ldcs4(p4 + i);
        float4 b0 = ldcs4(w4 + i);
        float4 a1 = ldcs4(p4 + i + stride);
        float4 b1 = ldcs4(w4 + i + stride);

        acc0 += __cosf(a0.x * b0.x);
        acc0 += __cosf(a0.y * b0.y);
        acc0 += __cosf(a0.z * b0.z);
        acc0 += __cosf(a0.w * b0.w);
        acc1 += __cosf(a1.x * b1.x);
        acc1 += __cosf(a1.y * b1.y);
        acc1 += __cosf(a1.z * b1.z);
        acc1 += __cosf(a1.w * b1.w);
    }
    // Remainder vector iterations
    for (; i < n4; i += stride) {
        float4 a = ldcs4(p4 + i);
        float4 b = ldcs4(w4 + i);
        acc0 += __cosf(a.x * b.x);
        acc0 += __cosf(a.y * b.y);
        acc0 += __cosf(a.z * b.z);
        acc0 += __cosf(a.w * b.w);
    }

    // Scalar tail (n_total not multiple of 4)
    long long ti = n4 * 4 + tid;
    if (ti < n_total) {
        acc0 += __cosf(phi[ti] * w[ti]);
    }

    float acc = acc0 + acc1;

    // Warp reduce
    #pragma unroll
    for (int o = 16; o > 0; o >>= 1)
        acc += __shfl_xor_sync(0xffffffffu, acc, o);

    __shared__ float smem[NTHREADS / 32];
    if ((threadIdx.x & 31) == 0)
        smem[threadIdx.x >> 5] = acc;
    __syncthreads();

    // Block partial -> global, then last block finishes
    __shared__ bool s_is_last;
    if (threadIdx.x == 0) {
        float v = 0.0f;
        #pragma unroll
        for (int k = 0; k < NTHREADS / 32; k++)
            v += smem[k];
        g_partials[blockIdx.x] = v;
        __threadfence();
        unsigned int ticket = atomicInc(&g_counter, NBLOCKS - 1);
        s_is_last = (ticket == NBLOCKS - 1);
    }
    __syncthreads();

    if (s_is_last) {
        float v = 0.0f;
        for (int k = threadIdx.x; k < NBLOCKS; k += NTHREADS)
            v += g_partials[k];

        #pragma unroll
        for (int o = 16; o > 0; o >>= 1)
            v += __shfl_xor_sync(0xffffffffu, v, o);

        if ((threadIdx.x & 31) == 0)
            smem[threadIdx.x >> 5] = v;
        __syncthreads();

        if (threadIdx.x < 32) {
            float t = (threadIdx.x < NTHREADS / 32) ? smem[threadIdx.x] : 0.0f;
            #pragma unroll
            for (int o = 4; o > 0; o >>= 1)
                t += __shfl_xor_sync(0xffffffffu, t, o);
            if (threadIdx.x == 0)
                out[0] = (t + bias) * inv_N;
        }
    }
}

extern "C" void kernel_launch(void* const* d_in, const int* in_sizes, int n_in,
                              void* d_out, int out_size) {
    const float* phi = (const float*)d_in[0];
    const float* w   = (const float*)d_in[1];

    long long C = (long long)in_sizes[0];

    int n = 0;
    while ((1LL << n) < C) n++;
    long long N = 1LL << n;

    float bias  = (float)(double)(N - C);
    float inv_N = (float)(1.0 / (double)N);

    long long n4 = C / 4;

    qsum_fused_kernel<<<NBLOCKS, NTHREADS>>>(phi, w, n4, C, bias, inv_N,
                                             (float*)d_out);
}

// round 4
// speedup vs baseline: 1.0398x; 1.0398x over previous
#include <cuda_runtime.h>

#define NBLOCKS 1184
#define NTHREADS 256

__device__ float        g_partials[NBLOCKS];
__device__ unsigned int g_counter = 0;   // self-resetting via atomicInc wrap

__global__ __launch_bounds__(NTHREADS, 8)
void qsum_fused_kernel(const float* __restrict__ phi,
                       const float* __restrict__ w,
                       int n4, int n_total,
                       float bias, float inv_N,
                       float* __restrict__ out) {
    const float4* __restrict__ p4 = reinterpret_cast<const float4*>(phi);
    const float4* __restrict__ w4 = reinterpret_cast<const float4*>(w);

    float acc = 0.0f;
    int tid    = blockIdx.x * NTHREADS + threadIdx.x;
    int stride = gridDim.x * NTHREADS;

    // Grid-stride loop: 2x LDG.128 per iter, evict-streaming (single-use data)
    for (int i = tid; i < n4; i += stride) {
        float4 a = __ldcs(p4 + i);
        float4 b = __ldcs(w4 + i);
        acc += __cosf(a.x * b.x);
        acc += __cosf(a.y * b.y);
        acc += __cosf(a.z * b.z);
        acc += __cosf(a.w * b.w);
    }

    // Scalar tail (n_total not multiple of 4)
    int ti = n4 * 4 + tid;
    if (ti < n_total) {
        acc += __cosf(phi[ti] * w[ti]);
    }

    // Warp reduce
    #pragma unroll
    for (int o = 16; o > 0; o >>= 1)
        acc += __shfl_xor_sync(0xffffffffu, acc, o);

    __shared__ float smem[NTHREADS / 32];
    if ((threadIdx.x & 31) == 0)
        smem[threadIdx.x >> 5] = acc;
    __syncthreads();

    // Block partial -> global, then last block finishes
    __shared__ bool s_is_last;
    if (threadIdx.x == 0) {
        float v = 0.0f;
        #pragma unroll
        for (int k = 0; k < NTHREADS / 32; k++)
            v += smem[k];
        g_partials[blockIdx.x] = v;
        __threadfence();
        unsigned int ticket = atomicInc(&g_counter, NBLOCKS - 1);
        s_is_last = (ticket == NBLOCKS - 1);
    }
    __syncthreads();

    if (s_is_last) {
        // Deterministic final reduction: fixed strided assignment + fixed tree
        float v = 0.0f;
        for (int k = threadIdx.x; k < NBLOCKS; k += NTHREADS)
            v += g_partials[k];

        #pragma unroll
        for (int o = 16; o > 0; o >>= 1)
            v += __shfl_xor_sync(0xffffffffu, v, o);

        if ((threadIdx.x & 31) == 0)
            smem[threadIdx.x >> 5] = v;
        __syncthreads();

        if (threadIdx.x < 32) {
            float t = (threadIdx.x < NTHREADS / 32) ? smem[threadIdx.x] : 0.0f;
            #pragma unroll
            for (int o = 4; o > 0; o >>= 1)
                t += __shfl_xor_sync(0xffffffffu, t, o);
            if (threadIdx.x == 0)
                out[0] = (t + bias) * inv_N;
        }
    }
}

extern "C" void kernel_launch(void* const* d_in, const int* in_sizes, int n_in,
                              void* d_out, int out_size) {
    const float* phi = (const float*)d_in[0];
    const float* w   = (const float*)d_in[1];

    long long C = (long long)in_sizes[0];

    // N = 2^ceil(log2(C))
    int n = 0;
    while ((1LL << n) < C) n++;
    long long N = 1LL << n;

    float bias  = (float)(double)(N - C);
    float inv_N = (float)(1.0 / (double)N);

    int n4 = (int)(C / 4);

    qsum_fused_kernel<<<NBLOCKS, NTHREADS>>>(phi, w, n4, (int)C, bias, inv_N,
                                             (float*)d_out);
}